// round 12
// baseline (speedup 1.0000x reference)
#include <cuda_runtime.h>

#define NC 16
#define EPSV 1e-6f
#define B_DIM 2
#define D_DIM 8
#define H_DIM 96
#define W_DIM 96
#define DHW (D_DIM*H_DIM*W_DIM)     // 73728
#define HW  (H_DIM*W_DIM)           // 9216

// CTA tile: full depth x 4 y x 8 x
#define TD 8
#define TH 4
#define TW 8
#define NTHREADS (TD*TH*TW)         // 256
#define HALO_D (TD+2)               // 10
#define HALO_H (TH+2)               // 6
#define HALO_W (TW+2)               // 10
#define NLOC   (HALO_D*HALO_H*HALO_W) // 600 halo locations
#define CSTRIDE 20                  // 16 ch + 4 pad floats (conflict-free LDS.128)
#define PLANE  (HALO_H*HALO_W*CSTRIDE)
#define SH_ELEMS (NLOC*CSTRIDE)     // 12000 floats = 48000 B
#define SV_ELEMS (27*NTHREADS)      // 6912 floats  = 27648 B
#define SW_OFF   (SH_ELEMS + SV_ELEMS)
#define SMEM_FLOATS (SW_OFF + 256)  // shared head/tail weight buffer
#define SMEM_BYTES (SMEM_FLOATS * 4)   // 76,672 B -> 3 CTAs/SM

typedef unsigned long long ull;

// ---- packed f32x2 helpers (Blackwell FFMA2 path, PTX-only) ----
__device__ __forceinline__ ull f2fma(ull a, ull b, ull c) {
    ull d; asm("fma.rn.f32x2 %0,%1,%2,%3;" : "=l"(d) : "l"(a), "l"(b), "l"(c)); return d;
}
__device__ __forceinline__ ull f2add(ull a, ull b) {
    ull d; asm("add.rn.f32x2 %0,%1,%2;" : "=l"(d) : "l"(a), "l"(b)); return d;
}
__device__ __forceinline__ ull f2mul(ull a, ull b) {
    ull d; asm("mul.rn.f32x2 %0,%1,%2;" : "=l"(d) : "l"(a), "l"(b)); return d;
}
__device__ __forceinline__ ull pack2(float lo, float hi) {
    ull d; asm("mov.b64 %0,{%1,%2};" : "=l"(d) : "f"(lo), "f"(hi)); return d;
}
__device__ __forceinline__ float2 unpack2(ull a) {
    float2 r; asm("mov.b64 {%0,%1},%2;" : "=f"(r.x), "=f"(r.y) : "l"(a)); return r;
}

// ---------------------------------------------------------------------------
// Single fused kernel: in-tile head GEMV (packed) -> smem, NMF, tail.
// ---------------------------------------------------------------------------
__global__ void __launch_bounds__(NTHREADS, 3)
nmf_kernel(const float* __restrict__ x,
           const float* __restrict__ head_w,
           const float* __restrict__ tail_w,
           float* __restrict__ out) {
    extern __shared__ float smem[];
    float* sh = smem;                 // [p][yy][xx][CSTRIDE] h halo tile (fp32)
    float* sv = smem + SH_ELEMS;      // [27][256] per-thread v (after staging)
    float* sw = smem + SW_OFF;        // [256] tail weights
    // During staging only: first 1KB of the (not yet used) sv region holds the
    // head weights packed as output-pairs: swp[j*16+c] = (w[2j][c], w[2j+1][c]).
    ull* swp = (ull*)sv;

    const int tid = threadIdx.x;
    const int b  = blockIdx.z;
    const int y0 = blockIdx.y * TH;
    const int x0 = blockIdx.x * TW;

    // ---- phase 0: packed head weights; tail weights into sw ----
    if (tid < 128) {
        int j = tid >> 4, c = tid & 15;
        swp[tid] = pack2(head_w[(2*j) * NC + c], head_w[(2*j+1) * NC + c]);
    }
    if (tid < NC * NC) sw[tid] = tail_w[tid];
    __syncthreads();

    // ---- staging: fused head GEMV (packed pairs) for the halo tile ----
    {
        const size_t xbase = (size_t)b * NC * DHW;
        for (int i = tid; i < NLOC; i += NTHREADS) {
            int xx = i % HALO_W;
            int r  = i / HALO_W;
            int yy = r % HALO_H;
            int p  = r / HALO_H;                       // d-plane 0..9
            int gd = min(max(p - 1, 0), D_DIM - 1);
            int gy = min(max(y0 + yy - 1, 0), H_DIM - 1);
            int gx = min(max(x0 + xx - 1, 0), W_DIM - 1);
            const float* xp = x + xbase + (size_t)(gd * HW + gy * W_DIM + gx);

            ull xv2[NC];
#pragma unroll
            for (int c = 0; c < NC; c++) {
                float v = xp[(size_t)c * DHW];
                xv2[c] = pack2(v, v);
            }

            ull acc[8];
#pragma unroll
            for (int j = 0; j < 8; j++) acc[j] = 0ull;
#pragma unroll
            for (int c = 0; c < NC; c++) {
#pragma unroll
                for (int j = 0; j < 8; j++)
                    acc[j] = f2fma(swp[j * NC + c], xv2[c], acc[j]);
            }

            float4* dst = (float4*)(sh + i * CSTRIDE);
#pragma unroll
            for (int q = 0; q < 2; q++) {
                float2 a0 = unpack2(acc[4*q+0]);
                float2 a1 = unpack2(acc[4*q+1]);
                float2 a2 = unpack2(acc[4*q+2]);
                float2 a3 = unpack2(acc[4*q+3]);
                dst[2*q+0] = make_float4(fmaxf(a0.x, 0.f), fmaxf(a0.y, 0.f),
                                         fmaxf(a1.x, 0.f), fmaxf(a1.y, 0.f));
                dst[2*q+1] = make_float4(fmaxf(a2.x, 0.f), fmaxf(a2.y, 0.f),
                                         fmaxf(a3.x, 0.f), fmaxf(a3.y, 0.f));
            }
        }
    }
    __syncthreads();   // staging done; sv region becomes the v store now

    const int tx = tid & 7;
    const int ty = (tid >> 3) & 3;
    const int td = tid >> 5;
    const float* shp = sh + ((td * HALO_H + ty) * HALO_W + tx) * CSTRIDE;

    ull up[8];
#pragma unroll
    for (int j = 0; j < 8; j++) up[j] = 0ull;   // two packed 0.0f

    // ---- init pass: u[c] = mean_k X, v[k] = mean_c X ----
#pragma unroll 1
    for (int kk = 0; kk < 9; kk++) {            // kk = ki*3+kj
        const int ki = kk / 3, kj = kk - 3 * ki;
        const float* pbase = shp + (ki * HALO_W + kj) * CSTRIDE;
        const int svb = kk * 3 * NTHREADS + tid;
#pragma unroll
        for (int kt = 0; kt < 3; kt++) {
            const ulonglong2* p = (const ulonglong2*)(pbase + kt * PLANE);
            ulonglong2 q0 = p[0], q1 = p[1], q2 = p[2], q3 = p[3];
            ull xp[8] = {q0.x, q0.y, q1.x, q1.y, q2.x, q2.y, q3.x, q3.y};
#pragma unroll
            for (int j = 0; j < 8; j++) up[j] = f2add(up[j], xp[j]);
            ull t0 = f2add(xp[0], xp[1]);
            ull t1 = f2add(xp[2], xp[3]);
            ull t2 = f2add(xp[4], xp[5]);
            ull t3 = f2add(xp[6], xp[7]);
            t0 = f2add(t0, t1); t2 = f2add(t2, t3);
            float2 s2 = unpack2(f2add(t0, t2));
            sv[svb + kt * NTHREADS] = (s2.x + s2.y) * (1.f / 16.f);
        }
    }
    {
        const ull c27 = pack2(1.f / 27.f, 1.f / 27.f);
#pragma unroll
        for (int j = 0; j < 8; j++) up[j] = f2mul(up[j], c27);
    }

    // ---- 3 NMF steps ----
#pragma unroll 1
    for (int step = 0; step < 3; step++) {
        ull uup = 0ull;
#pragma unroll
        for (int j = 0; j < 8; j++) uup = f2fma(up[j], up[j], uup);
        float2 uu2 = unpack2(uup);
        const float t_uu = 3.f * (uu2.x + uu2.y);
        const bool keep_all = (step < 2);

        ull nup[8];
#pragma unroll
        for (int j = 0; j < 8; j++) nup[j] = 0ull;
        float vv = 0.f;

#pragma unroll 1
        for (int kk = 0; kk < 9; kk++) {
            const int ki = kk / 3, kj = kk - 3 * ki;
            const float* pbase = shp + (ki * HALO_W + kj) * CSTRIDE;
            const int svb = kk * 3 * NTHREADS + tid;
#pragma unroll
            for (int kt = 0; kt < 3; kt++) {
                const ulonglong2* p = (const ulonglong2*)(pbase + kt * PLANE);
                ulonglong2 q0 = p[0], q1 = p[1], q2 = p[2], q3 = p[3];
                ull xp[8] = {q0.x, q0.y, q1.x, q1.y, q2.x, q2.y, q3.x, q3.y};

                // num = u . X[:,k]  (2 packed chains)
                ull np0 = f2mul(up[0], xp[0]);
                np0 = f2fma(up[2], xp[2], np0);
                np0 = f2fma(up[4], xp[4], np0);
                np0 = f2fma(up[6], xp[6], np0);
                ull np1 = f2mul(up[1], xp[1]);
                np1 = f2fma(up[3], xp[3], np1);
                np1 = f2fma(up[5], xp[5], np1);
                np1 = f2fma(up[7], xp[7], np1);
                float2 ns = unpack2(f2add(np0, np1));
                float num = ns.x + ns.y;

                const int svi = svb + kt * NTHREADS;
                float vk = sv[svi];
                float vn = vk * num * __frcp_rn(fmaf(t_uu, vk, EPSV));
                // last step: only v[13] (kk==4, kt==1) is ever read again
                if (keep_all || (kt == 1 && kk == 4)) sv[svi] = vn;
                vv = fmaf(vn, vn, vv);
                ull vn2 = pack2(vn, vn);
#pragma unroll
                for (int j = 0; j < 8; j++) nup[j] = f2fma(xp[j], vn2, nup[j]);
            }
        }
        const float t_vv = 3.f * vv;
#pragma unroll
        for (int j = 0; j < 8; j++) {
            float2 a  = unpack2(up[j]);
            float2 nb = unpack2(nup[j]);
            float c0 = a.x * nb.x * __frcp_rn(fmaf(t_vv, a.x, EPSV));
            float c1 = a.y * nb.y * __frcp_rn(fmaf(t_vv, a.y, EPSV));
            up[j] = pack2(c0, c1);
        }
    }

    // ---- center tap + tail GEMV + relu (packed) ----
    const float v13 = sv[13 * NTHREADS + tid];
    const ull v13p = pack2(3.f * v13, 3.f * v13);
    ull uvcp[8];
#pragma unroll
    for (int j = 0; j < 8; j++) uvcp[j] = f2mul(up[j], v13p);

    const size_t outbase = (size_t)b * NC * DHW + (size_t)td * HW
                         + (size_t)(y0 + ty) * W_DIM + (x0 + tx);
#pragma unroll
    for (int i = 0; i < NC; i++) {
        const ulonglong2* wr = (const ulonglong2*)(sw + i * NC);
        ulonglong2 w0 = wr[0], w1 = wr[1], w2 = wr[2], w3 = wr[3];
        ull acc0 = f2mul(w0.x, uvcp[0]);
        acc0 = f2fma(w1.x, uvcp[2], acc0);
        acc0 = f2fma(w2.x, uvcp[4], acc0);
        acc0 = f2fma(w3.x, uvcp[6], acc0);
        ull acc1 = f2mul(w0.y, uvcp[1]);
        acc1 = f2fma(w1.y, uvcp[3], acc1);
        acc1 = f2fma(w2.y, uvcp[5], acc1);
        acc1 = f2fma(w3.y, uvcp[7], acc1);
        float2 r2 = unpack2(f2add(acc0, acc1));
        out[outbase + (size_t)i * DHW] = fmaxf(r2.x + r2.y, 0.f);
    }
}

// ---------------------------------------------------------------------------
extern "C" void kernel_launch(void* const* d_in, const int* in_sizes, int n_in,
                              void* d_out, int out_size) {
    const float* x      = (const float*)d_in[0];
    const float* head_w = (const float*)d_in[1];
    const float* tail_w = (const float*)d_in[2];
    float* out = (float*)d_out;

    (void)in_sizes; (void)n_in; (void)out_size;

    cudaFuncSetAttribute(nmf_kernel,
                         cudaFuncAttributeMaxDynamicSharedMemorySize,
                         SMEM_BYTES);
    cudaFuncSetAttribute(nmf_kernel,
                         cudaFuncAttributePreferredSharedMemoryCarveout,
                         100);

    dim3 grid(W_DIM / TW, H_DIM / TH, B_DIM);   // (12, 24, 2) = 576 CTAs
    nmf_kernel<<<grid, NTHREADS, SMEM_BYTES>>>(x, head_w, tail_w, out);
}

// round 13
// speedup vs baseline: 1.0399x; 1.0399x over previous
#include <cuda_runtime.h>

#define NC 16
#define EPSV 1e-6f
#define B_DIM 2
#define D_DIM 8
#define H_DIM 96
#define W_DIM 96
#define DHW (D_DIM*H_DIM*W_DIM)     // 73728
#define HW  (H_DIM*W_DIM)           // 9216

// CTA tile: full depth x 4 y x 8 x
#define TD 8
#define TH 4
#define TW 8
#define NTHREADS (TD*TH*TW)         // 256
#define HALO_D (TD+2)               // 10
#define HALO_H (TH+2)               // 6
#define HALO_W (TW+2)               // 10
#define NLOC   (HALO_D*HALO_H*HALO_W) // 600 halo locations
#define CSTRIDE 20                  // 16 ch + 4 pad floats (conflict-free LDS.128)
#define PLANE  (HALO_H*HALO_W*CSTRIDE)
#define SH_ELEMS (NLOC*CSTRIDE)     // 12000 floats = 48000 B
#define SV_ELEMS (27*NTHREADS)      // 6912 floats  = 27648 B
#define SW_OFF   (SH_ELEMS + SV_ELEMS)
#define SMEM_FLOATS (SW_OFF + 256)
#define SMEM_BYTES (SMEM_FLOATS * 4)   // 76,672 B -> 3 CTAs/SM

#define NS_LOC (HALO_D * TH * TW)   // 320 spatial-box-sum locations

typedef unsigned long long ull;

// ---- packed f32x2 helpers (Blackwell FFMA2 path, PTX-only) ----
__device__ __forceinline__ ull f2fma(ull a, ull b, ull c) {
    ull d; asm("fma.rn.f32x2 %0,%1,%2,%3;" : "=l"(d) : "l"(a), "l"(b), "l"(c)); return d;
}
__device__ __forceinline__ ull f2add(ull a, ull b) {
    ull d; asm("add.rn.f32x2 %0,%1,%2;" : "=l"(d) : "l"(a), "l"(b)); return d;
}
__device__ __forceinline__ ull f2mul(ull a, ull b) {
    ull d; asm("mul.rn.f32x2 %0,%1,%2;" : "=l"(d) : "l"(a), "l"(b)); return d;
}
__device__ __forceinline__ ull pack2(float lo, float hi) {
    ull d; asm("mov.b64 %0,{%1,%2};" : "=l"(d) : "f"(lo), "f"(hi)); return d;
}
__device__ __forceinline__ float2 unpack2(ull a) {
    float2 r; asm("mov.b64 {%0,%1},%2;" : "=f"(r.x), "=f"(r.y) : "l"(a)); return r;
}

// ---------------------------------------------------------------------------
// Single fused kernel: head GEMV -> smem, box-filter u-init, 3 NMF sweeps, tail.
// ---------------------------------------------------------------------------
__global__ void __launch_bounds__(NTHREADS, 3)
nmf_kernel(const float* __restrict__ x,
           const float* __restrict__ head_w,
           const float* __restrict__ tail_w,
           float* __restrict__ out) {
    extern __shared__ float smem[];
    float* sh = smem;                 // [p][yy][xx][CSTRIDE] h halo tile (fp32)
    float* sv = smem + SH_ELEMS;      // scratch: S box sums, then per-thread v
    float* sw = smem + SW_OFF;        // [256] head weights, then tail weights

    const int tid = threadIdx.x;
    const int b  = blockIdx.z;
    const int y0 = blockIdx.y * TH;
    const int x0 = blockIdx.x * TW;

    // ---- phase 0: head weights ----
    if (tid < NC * NC) sw[tid] = head_w[tid];
    __syncthreads();

    // ---- staging: fused head GEMV for the 600-location halo tile ----
    {
        const size_t xbase = (size_t)b * NC * DHW;
        for (int i = tid; i < NLOC; i += NTHREADS) {
            int xx = i % HALO_W;
            int r  = i / HALO_W;
            int yy = r % HALO_H;
            int p  = r / HALO_H;                       // d-plane 0..9
            int gd = min(max(p - 1, 0), D_DIM - 1);
            int gy = min(max(y0 + yy - 1, 0), H_DIM - 1);
            int gx = min(max(x0 + xx - 1, 0), W_DIM - 1);
            const float* xp = x + xbase + (size_t)(gd * HW + gy * W_DIM + gx);

            float xv[NC];
#pragma unroll
            for (int c = 0; c < NC; c++) xv[c] = xp[(size_t)c * DHW];

            float4* dst = (float4*)(sh + i * CSTRIDE);
#pragma unroll
            for (int q = 0; q < 4; q++) {
                float h0 = 0.f, h1 = 0.f, h2 = 0.f, h3 = 0.f;
#pragma unroll
                for (int c = 0; c < NC; c++) {
                    h0 = fmaf(sw[(4*q+0) * NC + c], xv[c], h0);
                    h1 = fmaf(sw[(4*q+1) * NC + c], xv[c], h1);
                    h2 = fmaf(sw[(4*q+2) * NC + c], xv[c], h2);
                    h3 = fmaf(sw[(4*q+3) * NC + c], xv[c], h3);
                }
                dst[q] = make_float4(fmaxf(h0, 0.f), fmaxf(h1, 0.f),
                                     fmaxf(h2, 0.f), fmaxf(h3, 0.f));
            }
        }
    }
    __syncthreads();

    // ---- box phase 1: spatial 3x3 column sums S(d, iy, ix, c) into sv ----
    // (sw swap to tail weights rides between the same barriers)
    if (tid < NC * NC) sw[tid] = tail_w[tid];
    for (int l = tid; l < NS_LOC; l += NTHREADS) {
        int d  = l >> 5;              // halo d-plane 0..9
        int rr = l & 31;
        int iy = rr >> 3;             // 0..3 (tile y)
        int ix = rr & 7;              // 0..7 (tile x)
        ull acc[8];
#pragma unroll
        for (int j = 0; j < 8; j++) acc[j] = 0ull;
#pragma unroll
        for (int ki = 0; ki < 3; ki++) {
#pragma unroll
            for (int kj = 0; kj < 3; kj++) {
                const ulonglong2* p = (const ulonglong2*)(sh
                    + ((d * HALO_H + iy + ki) * HALO_W + (ix + kj)) * CSTRIDE);
                ulonglong2 q0 = p[0], q1 = p[1], q2 = p[2], q3 = p[3];
                acc[0] = f2add(acc[0], q0.x); acc[1] = f2add(acc[1], q0.y);
                acc[2] = f2add(acc[2], q1.x); acc[3] = f2add(acc[3], q1.y);
                acc[4] = f2add(acc[4], q2.x); acc[5] = f2add(acc[5], q2.y);
                acc[6] = f2add(acc[6], q3.x); acc[7] = f2add(acc[7], q3.y);
            }
        }
        ulonglong2* dst = (ulonglong2*)(sv + l * CSTRIDE);
        dst[0] = make_ulonglong2(acc[0], acc[1]);
        dst[1] = make_ulonglong2(acc[2], acc[3]);
        dst[2] = make_ulonglong2(acc[4], acc[5]);
        dst[3] = make_ulonglong2(acc[6], acc[7]);
    }
    __syncthreads();

    const int tx = tid & 7;
    const int ty = (tid >> 3) & 3;
    const int td = tid >> 5;
    const float* shp = sh + ((td * HALO_H + ty) * HALO_W + tx) * CSTRIDE;

    // ---- box phase 2: u0 = (S(td) + S(td+1) + S(td+2)) / 27 ----
    ull up[8];
#pragma unroll
    for (int j = 0; j < 8; j++) up[j] = 0ull;
#pragma unroll
    for (int kt = 0; kt < 3; kt++) {
        const ulonglong2* p = (const ulonglong2*)(sv
            + ((td + kt) * 32 + ty * 8 + tx) * CSTRIDE);
        ulonglong2 q0 = p[0], q1 = p[1], q2 = p[2], q3 = p[3];
        up[0] = f2add(up[0], q0.x); up[1] = f2add(up[1], q0.y);
        up[2] = f2add(up[2], q1.x); up[3] = f2add(up[3], q1.y);
        up[4] = f2add(up[4], q2.x); up[5] = f2add(up[5], q2.y);
        up[6] = f2add(up[6], q3.x); up[7] = f2add(up[7], q3.y);
    }
    {
        const ull c27 = pack2(1.f / 27.f, 1.f / 27.f);
#pragma unroll
        for (int j = 0; j < 8; j++) up[j] = f2mul(up[j], c27);
    }
    __syncthreads();   // S reads done; sv becomes the v store

    // ---- NMF step 1 (peeled: v0 computed in-flight from the column) ----
    {
        ull uup = 0ull;
#pragma unroll
        for (int j = 0; j < 8; j++) uup = f2fma(up[j], up[j], uup);
        float2 uu2 = unpack2(uup);
        const float t_uu = 3.f * (uu2.x + uu2.y);

        ull nup[8];
#pragma unroll
        for (int j = 0; j < 8; j++) nup[j] = 0ull;
        float vv = 0.f;

#pragma unroll 1
        for (int kk = 0; kk < 9; kk++) {
            const int ki = kk / 3, kj = kk - 3 * ki;
            const float* pbase = shp + (ki * HALO_W + kj) * CSTRIDE;
            const int svb = kk * 3 * NTHREADS + tid;
#pragma unroll
            for (int kt = 0; kt < 3; kt++) {
                const ulonglong2* p = (const ulonglong2*)(pbase + kt * PLANE);
                ulonglong2 q0 = p[0], q1 = p[1], q2 = p[2], q3 = p[3];
                ull xp[8] = {q0.x, q0.y, q1.x, q1.y, q2.x, q2.y, q3.x, q3.y};

                // v0 = mean_c of this column (same add tree as the old init)
                ull t0 = f2add(xp[0], xp[1]);
                ull t1 = f2add(xp[2], xp[3]);
                ull t2 = f2add(xp[4], xp[5]);
                ull t3 = f2add(xp[6], xp[7]);
                t0 = f2add(t0, t1); t2 = f2add(t2, t3);
                float2 s2 = unpack2(f2add(t0, t2));
                float vk = (s2.x + s2.y) * (1.f / 16.f);

                // num = u . X[:,k]
                ull np0 = f2mul(up[0], xp[0]);
                np0 = f2fma(up[2], xp[2], np0);
                np0 = f2fma(up[4], xp[4], np0);
                np0 = f2fma(up[6], xp[6], np0);
                ull np1 = f2mul(up[1], xp[1]);
                np1 = f2fma(up[3], xp[3], np1);
                np1 = f2fma(up[5], xp[5], np1);
                np1 = f2fma(up[7], xp[7], np1);
                float2 ns = unpack2(f2add(np0, np1));
                float num = ns.x + ns.y;

                float vn = vk * num * __frcp_rn(fmaf(t_uu, vk, EPSV));
                sv[svb + kt * NTHREADS] = vn;
                vv = fmaf(vn, vn, vv);
                ull vn2 = pack2(vn, vn);
#pragma unroll
                for (int j = 0; j < 8; j++) nup[j] = f2fma(xp[j], vn2, nup[j]);
            }
        }
        const float t_vv = 3.f * vv;
#pragma unroll
        for (int j = 0; j < 8; j++) {
            float2 a  = unpack2(up[j]);
            float2 nb = unpack2(nup[j]);
            float c0 = a.x * nb.x * __frcp_rn(fmaf(t_vv, a.x, EPSV));
            float c1 = a.y * nb.y * __frcp_rn(fmaf(t_vv, a.y, EPSV));
            up[j] = pack2(c0, c1);
        }
    }

    // ---- NMF steps 2..3 (v from sv) ----
#pragma unroll 1
    for (int s = 0; s < 2; s++) {
        ull uup = 0ull;
#pragma unroll
        for (int j = 0; j < 8; j++) uup = f2fma(up[j], up[j], uup);
        float2 uu2 = unpack2(uup);
        const float t_uu = 3.f * (uu2.x + uu2.y);
        const bool keep_all = (s == 0);

        ull nup[8];
#pragma unroll
        for (int j = 0; j < 8; j++) nup[j] = 0ull;
        float vv = 0.f;

#pragma unroll 1
        for (int kk = 0; kk < 9; kk++) {
            const int ki = kk / 3, kj = kk - 3 * ki;
            const float* pbase = shp + (ki * HALO_W + kj) * CSTRIDE;
            const int svb = kk * 3 * NTHREADS + tid;
#pragma unroll
            for (int kt = 0; kt < 3; kt++) {
                const ulonglong2* p = (const ulonglong2*)(pbase + kt * PLANE);
                ulonglong2 q0 = p[0], q1 = p[1], q2 = p[2], q3 = p[3];
                ull xp[8] = {q0.x, q0.y, q1.x, q1.y, q2.x, q2.y, q3.x, q3.y};

                ull np0 = f2mul(up[0], xp[0]);
                np0 = f2fma(up[2], xp[2], np0);
                np0 = f2fma(up[4], xp[4], np0);
                np0 = f2fma(up[6], xp[6], np0);
                ull np1 = f2mul(up[1], xp[1]);
                np1 = f2fma(up[3], xp[3], np1);
                np1 = f2fma(up[5], xp[5], np1);
                np1 = f2fma(up[7], xp[7], np1);
                float2 ns = unpack2(f2add(np0, np1));
                float num = ns.x + ns.y;

                const int svi = svb + kt * NTHREADS;
                float vk = sv[svi];
                float vn = vk * num * __frcp_rn(fmaf(t_uu, vk, EPSV));
                if (keep_all || (kt == 1 && kk == 4)) sv[svi] = vn;
                vv = fmaf(vn, vn, vv);
                ull vn2 = pack2(vn, vn);
#pragma unroll
                for (int j = 0; j < 8; j++) nup[j] = f2fma(xp[j], vn2, nup[j]);
            }
        }
        const float t_vv = 3.f * vv;
#pragma unroll
        for (int j = 0; j < 8; j++) {
            float2 a  = unpack2(up[j]);
            float2 nb = unpack2(nup[j]);
            float c0 = a.x * nb.x * __frcp_rn(fmaf(t_vv, a.x, EPSV));
            float c1 = a.y * nb.y * __frcp_rn(fmaf(t_vv, a.y, EPSV));
            up[j] = pack2(c0, c1);
        }
    }

    // ---- center tap + tail GEMV + relu (packed) ----
    const float v13 = sv[13 * NTHREADS + tid];
    const ull v13p = pack2(3.f * v13, 3.f * v13);
    ull uvcp[8];
#pragma unroll
    for (int j = 0; j < 8; j++) uvcp[j] = f2mul(up[j], v13p);

    const size_t outbase = (size_t)b * NC * DHW + (size_t)td * HW
                         + (size_t)(y0 + ty) * W_DIM + (x0 + tx);
#pragma unroll
    for (int i = 0; i < NC; i++) {
        const ulonglong2* wr = (const ulonglong2*)(sw + i * NC);
        ulonglong2 w0 = wr[0], w1 = wr[1], w2 = wr[2], w3 = wr[3];
        ull acc0 = f2mul(w0.x, uvcp[0]);
        acc0 = f2fma(w1.x, uvcp[2], acc0);
        acc0 = f2fma(w2.x, uvcp[4], acc0);
        acc0 = f2fma(w3.x, uvcp[6], acc0);
        ull acc1 = f2mul(w0.y, uvcp[1]);
        acc1 = f2fma(w1.y, uvcp[3], acc1);
        acc1 = f2fma(w2.y, uvcp[5], acc1);
        acc1 = f2fma(w3.y, uvcp[7], acc1);
        float2 r2 = unpack2(f2add(acc0, acc1));
        out[outbase + (size_t)i * DHW] = fmaxf(r2.x + r2.y, 0.f);
    }
}

// ---------------------------------------------------------------------------
extern "C" void kernel_launch(void* const* d_in, const int* in_sizes, int n_in,
                              void* d_out, int out_size) {
    const float* x      = (const float*)d_in[0];
    const float* head_w = (const float*)d_in[1];
    const float* tail_w = (const float*)d_in[2];
    float* out = (float*)d_out;

    (void)in_sizes; (void)n_in; (void)out_size;

    cudaFuncSetAttribute(nmf_kernel,
                         cudaFuncAttributeMaxDynamicSharedMemorySize,
                         SMEM_BYTES);
    cudaFuncSetAttribute(nmf_kernel,
                         cudaFuncAttributePreferredSharedMemoryCarveout,
                         100);

    dim3 grid(W_DIM / TW, H_DIM / TH, B_DIM);   // (12, 24, 2) = 576 CTAs
    nmf_kernel<<<grid, NTHREADS, SMEM_BYTES>>>(x, head_w, tail_w, out);
}